// round 2
// baseline (speedup 1.0000x reference)
#include <cuda_runtime.h>
#include <cstddef>

// ---------------- problem constants ----------------
#define BATCH 8
#define NCLS 80
#define ATOT 22743            // 76*76*3 + 38*38*3 + 19*19*3
#define NFLAT (ATOT * NCLS)   // 1,819,440 per batch
#define PRE_NMS 400
#define MAX_DET 100

// ---------------- static scratch (no runtime allocs allowed) ----------------
__device__ float g_x[46208 * 256];                         // tower activations (max level 0), 47MB
__device__ float g_boxes[BATCH * ATOT * 4];                // decoded boxes
__device__ float g_scores[(size_t)BATCH * NFLAT];          // decoded scores, 58MB
__device__ unsigned g_hist1[BATCH * 4096];
__device__ unsigned g_hist2[BATCH * 4096];
__device__ unsigned g_b1[BATCH];
__device__ unsigned g_prefix1[BATCH];
__device__ unsigned g_pivot[BATCH];
__device__ unsigned g_cnt[BATCH];
__device__ unsigned long long g_cand[BATCH * 8192];

__constant__ float c_anchors[3][3][2] = {
    {{12.f, 16.f}, {19.f, 36.f}, {40.f, 28.f}},
    {{36.f, 75.f}, {76.f, 55.f}, {72.f, 146.f}},
    {{142.f, 110.f}, {192.f, 243.f}, {459.f, 401.f}}};

__device__ __forceinline__ float sigmoidf_(float x) { return 1.0f / (1.0f + expf(-x)); }

// ---------------- init ----------------
__global__ void zero_misc() {
    int i = blockIdx.x * blockDim.x + threadIdx.x;
    if (i < BATCH * 4096) { g_hist1[i] = 0u; g_hist2[i] = 0u; }
    if (i < BATCH) {
        g_cnt[i] = 0u;
        g_b1[i] = 0u;
        g_prefix1[i] = 0u;
        g_pivot[i] = 0u;
    }
}

// ---------------- fused conv3x3 + scale/bias + leaky-relu ----------------
// Implicit-GEMM: M = BATCH*H*H output pixels, N = COUT, K = 9*CIN.
// BM=64, BN=64, BK=32, 256 threads, 4x4 microtile per thread.
template <int CIN, int COUT, int HH>
__global__ __launch_bounds__(256) void conv3x3(const float* __restrict__ in,
                                               const float* __restrict__ w,
                                               const float* __restrict__ gamma,
                                               const float* __restrict__ beta) {
    constexpr int M = BATCH * HH * HH;
    constexpr int KTOT = 9 * CIN;
    __shared__ float As[32][68];  // [k][m], padded
    __shared__ float Bs[32][68];  // [k][n], padded

    const int tid = threadIdx.x;
    const int bm0 = blockIdx.x * 64;
    const int bn0 = blockIdx.y * 64;

    // Precompute per-thread A-load pixel coordinates (2 float4 loads per thread)
    int aM[2], aB[2], aOy[2], aOx[2];
    bool aValid[2];
#pragma unroll
    for (int li = 0; li < 2; li++) {
        int id = li * 256 + tid;
        int m = id >> 3;
        aM[li] = m;
        int gm = bm0 + m;
        aValid[li] = (gm < M);
        int gmc = aValid[li] ? gm : 0;
        int b = gmc / (HH * HH);
        int rr = gmc % (HH * HH);
        aB[li] = b;
        aOy[li] = rr / HH;
        aOx[li] = rr % HH;
    }

    const int tm = (tid >> 4) * 4;
    const int tn = (tid & 15) * 4;
    float acc[4][4] = {};

    for (int kt = 0; kt < KTOT / 32; kt++) {
        int kk = kt * 32;
        int tap = kk / CIN;      // single 3x3 tap per k-tile since 32 | CIN
        int ciB = kk % CIN;
        int ky = tap / 3, kx = tap % 3;

        // load A (im2col on the fly)
#pragma unroll
        for (int li = 0; li < 2; li++) {
            int id = li * 256 + tid;
            int k = (id & 7) * 4;
            int iy = aOy[li] + ky - 1;
            int ix = aOx[li] + kx - 1;
            float4 v = make_float4(0.f, 0.f, 0.f, 0.f);
            if (aValid[li] && iy >= 0 && iy < HH && ix >= 0 && ix < HH)
                v = *(const float4*)&in[(((size_t)aB[li] * HH + iy) * HH + ix) * CIN + ciB + k];
            As[k + 0][aM[li]] = v.x;
            As[k + 1][aM[li]] = v.y;
            As[k + 2][aM[li]] = v.z;
            As[k + 3][aM[li]] = v.w;
        }
        // load B (weights, HWIO layout -> [(tap*CIN+ci)][COUT])
#pragma unroll
        for (int li = 0; li < 2; li++) {
            int id = li * 256 + tid;
            int k = id >> 4;
            int n = (id & 15) * 4;
            *(float4*)&Bs[k][n] = *(const float4*)&w[(size_t)(kk + k) * COUT + bn0 + n];
        }
        __syncthreads();

#pragma unroll
        for (int k = 0; k < 32; k++) {
            float4 a4 = *(float4*)&As[k][tm];
            float4 b4 = *(float4*)&Bs[k][tn];
            float av[4] = {a4.x, a4.y, a4.z, a4.w};
            float bv[4] = {b4.x, b4.y, b4.z, b4.w};
#pragma unroll
            for (int i = 0; i < 4; i++)
#pragma unroll
                for (int j = 0; j < 4; j++) acc[i][j] += av[i] * bv[j];
        }
        __syncthreads();
    }

    // epilogue: scale/bias + leaky relu (gamma=1, beta=0 in practice, but generic)
    float4 g4 = *(const float4*)&gamma[bn0 + tn];
    float4 bb4 = *(const float4*)&beta[bn0 + tn];
    float gv[4] = {g4.x, g4.y, g4.z, g4.w};
    float bv[4] = {bb4.x, bb4.y, bb4.z, bb4.w};
#pragma unroll
    for (int i = 0; i < 4; i++) {
        int gm = bm0 + tm + i;
        if (gm >= M) break;
        float4 o;
        float t0 = acc[i][0] * gv[0] + bv[0];
        float t1 = acc[i][1] * gv[1] + bv[1];
        float t2 = acc[i][2] * gv[2] + bv[2];
        float t3 = acc[i][3] * gv[3] + bv[3];
        o.x = t0 > 0.f ? t0 : 0.1f * t0;
        o.y = t1 > 0.f ? t1 : 0.1f * t1;
        o.z = t2 > 0.f ? t2 : 0.1f * t2;
        o.w = t3 > 0.f ? t3 : 0.1f * t3;
        *(float4*)&g_x[(size_t)gm * COUT + bn0 + tn] = o;
    }
}

// ---------------- 1x1 conv (255 ch) + bias + decode ----------------
// Each block handles 8 pixels; thread t<255 computes pred channel t for all 8.
template <int HD, int HH>
__global__ __launch_bounds__(256) void pred_decode(const float* __restrict__ w1,
                                                   const float* __restrict__ bias,
                                                   int levelOff, float stride, int alevel) {
    constexpr int P = 8;
    __shared__ float xsh[P][HD];
    __shared__ float psh[P][256];
    const int tid = threadIdx.x;
    const int pix0 = blockIdx.x * P;

    for (int id = tid; id < P * (HD / 4); id += 256) {
        int p = id / (HD / 4);
        int r = id % (HD / 4);
        *(float4*)&xsh[p][r * 4] = *(const float4*)&g_x[(size_t)(pix0 + p) * HD + r * 4];
    }
    __syncthreads();

    if (tid < 255) {
        float acc[P];
        float bb = bias[tid];
#pragma unroll
        for (int p = 0; p < P; p++) acc[p] = bb;
#pragma unroll 4
        for (int k = 0; k < HD; k++) {
            float wv = w1[(size_t)k * 255 + tid];
#pragma unroll
            for (int p = 0; p < P; p++) acc[p] += xsh[p][k] * wv;
        }
#pragma unroll
        for (int p = 0; p < P; p++) psh[p][tid] = acc[p];
    }
    __syncthreads();

    // scores: 8 pixels * 3 anchors * 80 classes
    for (int wi = tid; wi < P * 240; wi += 256) {
        int p = wi / 240, r = wi % 240;
        int a = r / 80, c = r % 80;
        float so = sigmoidf_(psh[p][a * 85 + 4]);
        float sc = sigmoidf_(psh[p][a * 85 + 5 + c]);
        int pix = pix0 + p;
        int b = pix / (HH * HH);
        int rr = pix % (HH * HH);
        size_t aidx = (size_t)b * ATOT + levelOff + rr * 3 + a;
        g_scores[aidx * NCLS + c] = so * sc;
    }
    // boxes: 8 pixels * 3 anchors
    for (int wi = tid; wi < P * 3; wi += 256) {
        int p = wi / 3, a = wi % 3;
        int pix = pix0 + p;
        int b = pix / (HH * HH);
        int rr = pix % (HH * HH);
        int oy = rr / HH, ox = rr % HH;
        float tx = psh[p][a * 85 + 0];
        float ty = psh[p][a * 85 + 1];
        float tw = psh[p][a * 85 + 2];
        float th = psh[p][a * 85 + 3];
        float cx = ((sigmoidf_(tx) * 1.05f - 0.025f) + (float)ox) * stride;
        float cy = ((sigmoidf_(ty) * 1.05f - 0.025f) + (float)oy) * stride;
        float bw = expf(tw) * c_anchors[alevel][a][0];
        float bh = expf(th) * c_anchors[alevel][a][1];
        size_t aidx = (size_t)b * ATOT + levelOff + rr * 3 + a;
        float* bp = &g_boxes[aidx * 4];
        bp[0] = cx - 0.5f * bw;
        bp[1] = cy - 0.5f * bh;
        bp[2] = cx + 0.5f * bw;
        bp[3] = cy + 0.5f * bh;
    }
}

// ---------------- top-400 selection: 2-level radix histogram on float bits ----------------
__global__ void hist1_kernel() {
    __shared__ unsigned h[4096];
    for (int i = threadIdx.x; i < 4096; i += blockDim.x) h[i] = 0u;
    __syncthreads();
    int b = blockIdx.y;
    const float* sc = &g_scores[(size_t)b * NFLAT];
    int start = blockIdx.x * 4096;
    int end = min(start + 4096, NFLAT);
    for (int i = start + (int)threadIdx.x; i < end; i += blockDim.x) {
        float s = sc[i];
        unsigned bits = (s >= 0.05f) ? __float_as_uint(s) : 0u;
        atomicAdd(&h[bits >> 20], 1u);
    }
    __syncthreads();
    for (int i = threadIdx.x; i < 4096; i += blockDim.x)
        if (h[i]) atomicAdd(&g_hist1[b * 4096 + i], h[i]);
}

__global__ void scan1_kernel() {
    __shared__ unsigned s[1024];
    int b = blockIdx.x, tid = threadIdx.x;
    unsigned v[4], sum = 0;
#pragma unroll
    for (int j = 0; j < 4; j++) {
        v[j] = g_hist1[b * 4096 + 4095 - (tid * 4 + j)];
        sum += v[j];
    }
    s[tid] = sum;
    __syncthreads();
    for (int off = 1; off < 1024; off <<= 1) {
        unsigned t = (tid >= off) ? s[tid - off] : 0u;
        __syncthreads();
        s[tid] += t;
        __syncthreads();
    }
    unsigned excl = s[tid] - sum;
    unsigned cum = excl;
#pragma unroll
    for (int j = 0; j < 4; j++) {
        if (cum < PRE_NMS && cum + v[j] >= PRE_NMS) {
            g_b1[b] = 4095 - (tid * 4 + j);
            g_prefix1[b] = cum;
        }
        cum += v[j];
    }
}

__global__ void hist2_kernel() {
    __shared__ unsigned h[4096];
    for (int i = threadIdx.x; i < 4096; i += blockDim.x) h[i] = 0u;
    __syncthreads();
    int b = blockIdx.y;
    unsigned b1 = g_b1[b];
    const float* sc = &g_scores[(size_t)b * NFLAT];
    int start = blockIdx.x * 4096;
    int end = min(start + 4096, NFLAT);
    for (int i = start + (int)threadIdx.x; i < end; i += blockDim.x) {
        float s = sc[i];
        unsigned bits = (s >= 0.05f) ? __float_as_uint(s) : 0u;
        if ((bits >> 20) == b1) atomicAdd(&h[(bits >> 8) & 0xFFFu], 1u);
    }
    __syncthreads();
    for (int i = threadIdx.x; i < 4096; i += blockDim.x)
        if (h[i]) atomicAdd(&g_hist2[b * 4096 + i], h[i]);
}

__global__ void scan2_kernel() {
    __shared__ unsigned s[1024];
    int b = blockIdx.x, tid = threadIdx.x;
    unsigned target = PRE_NMS - g_prefix1[b];  // >= 1 by construction
    unsigned v[4], sum = 0;
#pragma unroll
    for (int j = 0; j < 4; j++) {
        v[j] = g_hist2[b * 4096 + 4095 - (tid * 4 + j)];
        sum += v[j];
    }
    s[tid] = sum;
    __syncthreads();
    for (int off = 1; off < 1024; off <<= 1) {
        unsigned t = (tid >= off) ? s[tid - off] : 0u;
        __syncthreads();
        s[tid] += t;
        __syncthreads();
    }
    unsigned excl = s[tid] - sum;
    unsigned cum = excl;
#pragma unroll
    for (int j = 0; j < 4; j++) {
        if (cum < target && cum + v[j] >= target) {
            g_pivot[b] = (g_b1[b] << 12) | (unsigned)(4095 - (tid * 4 + j));
        }
        cum += v[j];
    }
}

__global__ void compact_kernel() {
    int b = blockIdx.y;
    unsigned pivot = g_pivot[b];
    const float* sc = &g_scores[(size_t)b * NFLAT];
    int start = blockIdx.x * 4096;
    int end = min(start + 4096, NFLAT);
    for (int i = start + (int)threadIdx.x; i < end; i += blockDim.x) {
        float s = sc[i];
        unsigned bits = (s >= 0.05f) ? __float_as_uint(s) : 0u;
        if ((bits >> 8) >= pivot) {
            unsigned pos = atomicAdd(&g_cnt[b], 1u);
            if (pos < 8192)
                g_cand[b * 8192 + pos] =
                    ((unsigned long long)bits << 32) |
                    (unsigned long long)(0xFFFFFFFFu - (unsigned)i);
        }
    }
}

// ---------------- exact top-k sort + greedy NMS + final top-100 ----------------
__global__ __launch_bounds__(512) void nms_kernel(float* __restrict__ out) {
    constexpr int NC = 2048;
    __shared__ unsigned long long keys[NC];
    __shared__ float boSh[PRE_NMS][4];
    __shared__ float areaSh[PRE_NMS];
    __shared__ float scSh[PRE_NMS];
    __shared__ int keepSh[PRE_NMS];
    __shared__ int aiSh[PRE_NMS];
    __shared__ int ciSh[PRE_NMS];
    __shared__ unsigned long long key2[512];

    int b = blockIdx.x;
    int tid = threadIdx.x;
    int cnt = min((int)g_cnt[b], NC);
    for (int i = tid; i < NC; i += 512)
        keys[i] = (i < cnt) ? g_cand[b * 8192 + i] : 0ull;
    __syncthreads();

    // bitonic ascending sort over NC composite keys (score_bits, ~flat_idx)
    for (int k = 2; k <= NC; k <<= 1) {
        for (int j = k >> 1; j > 0; j >>= 1) {
            for (int i = tid; i < NC; i += 512) {
                int ixj = i ^ j;
                if (ixj > i) {
                    bool up = ((i & k) == 0);
                    unsigned long long a = keys[i], c = keys[ixj];
                    if (up ? (a > c) : (a < c)) { keys[i] = c; keys[ixj] = a; }
                }
            }
            __syncthreads();
        }
    }

    // extract top-400 (descending), build offset boxes exactly like reference
    if (tid < PRE_NMS) {
        unsigned long long key = keys[NC - 1 - tid];
        unsigned bits = (unsigned)(key >> 32);
        unsigned flat = 0xFFFFFFFFu - (unsigned)(key & 0xFFFFFFFFull);
        if (key == 0ull) { bits = 0u; flat = 0u; }
        float s = __uint_as_float(bits);
        int a = (int)(flat / NCLS);
        int c = (int)(flat % NCLS);
        const float* bp = &g_boxes[((size_t)b * ATOT + a) * 4];
        float off = (float)c * 1216.0f;  // c * 2*IMG_SIZE
        float x0 = bp[0] + off, y0 = bp[1] + off;
        float x1 = bp[2] + off, y1 = bp[3] + off;
        boSh[tid][0] = x0; boSh[tid][1] = y0; boSh[tid][2] = x1; boSh[tid][3] = y1;
        areaSh[tid] = (x1 - x0) * (y1 - y0);
        scSh[tid] = s;
        keepSh[tid] = 1;
        aiSh[tid] = a;
        ciSh[tid] = c;
    }
    __syncthreads();

    // greedy suppression, iteration order = score rank (matches fori_loop)
    for (int i = 0; i < PRE_NMS; i++) {
        bool act = (keepSh[i] != 0) && (scSh[i] > 0.f);
        if (act && tid > i && tid < PRE_NMS) {
            float lx = fmaxf(boSh[i][0], boSh[tid][0]);
            float ly = fmaxf(boSh[i][1], boSh[tid][1]);
            float rx = fminf(boSh[i][2], boSh[tid][2]);
            float ry = fminf(boSh[i][3], boSh[tid][3]);
            float w = fmaxf(rx - lx, 0.f), h = fmaxf(ry - ly, 0.f);
            float inter = w * h;
            float iou = inter / (areaSh[i] + areaSh[tid] - inter + 1e-7f);
            if (iou > 0.5f) keepSh[tid] = 0;
        }
        __syncthreads();
    }

    // final scores + stable top-100
    {
        unsigned long long key = 0ull;
        if (tid < PRE_NMS) {
            float fin = (keepSh[tid] && scSh[tid] > 0.f) ? scSh[tid] : 0.f;
            key = ((unsigned long long)__float_as_uint(fin) << 32) |
                  (unsigned long long)(0xFFFFFFFFu - (unsigned)tid);
        }
        key2[tid] = key;
    }
    __syncthreads();
    for (int k = 2; k <= 512; k <<= 1) {
        for (int j = k >> 1; j > 0; j >>= 1) {
            int i = tid;
            int ixj = i ^ j;
            if (ixj > i) {
                bool up = ((i & k) == 0);
                unsigned long long a = key2[i], c = key2[ixj];
                if (up ? (a > c) : (a < c)) { key2[i] = c; key2[ixj] = a; }
            }
            __syncthreads();
        }
    }

    if (tid < MAX_DET) {
        unsigned long long key = key2[511 - tid];
        unsigned sb = (unsigned)(key >> 32);
        int pos = (int)(0xFFFFFFFFu - (unsigned)(key & 0xFFFFFFFFull));
        int a = aiSh[pos], c = ciSh[pos];
        const float* bp = &g_boxes[((size_t)b * ATOT + a) * 4];
        int d = b * MAX_DET + tid;
        out[d * 4 + 0] = bp[0];
        out[d * 4 + 1] = bp[1];
        out[d * 4 + 2] = bp[2];
        out[d * 4 + 3] = bp[3];
        out[BATCH * MAX_DET * 4 + d] = __uint_as_float(sb);
        out[BATCH * MAX_DET * 4 + BATCH * MAX_DET + d] = (float)c;
    }
}

// ---------------- launcher ----------------
extern "C" void kernel_launch(void* const* d_in, const int* in_sizes, int n_in,
                              void* d_out, int out_size) {
    (void)out_size;
    const float *f0 = nullptr, *f1 = nullptr, *f2 = nullptr;
    const float *w3[3] = {}, *ga[3] = {}, *be[3] = {}, *w1[3] = {}, *b1[3] = {};
    int c256 = 0, c512 = 0, c1024 = 0, c255 = 0;
    for (int i = 0; i < n_in; i++) {
        const float* p = (const float*)d_in[i];
        switch (in_sizes[i]) {
            case 5914624: f0 = p; break;                 // 8*76*76*128
            case 2957312: f1 = p; break;                 // 8*38*38*256
            case 1478656: f2 = p; break;                 // 8*19*19*512
            case 294912:  w3[0] = p; break;              // 3*3*128*256
            case 1179648: w3[1] = p; break;              // 3*3*256*512
            case 4718592: w3[2] = p; break;              // 3*3*512*1024
            case 65280:   w1[0] = p; break;              // 256*255
            case 130560:  w1[1] = p; break;              // 512*255
            case 261120:  w1[2] = p; break;              // 1024*255
            case 256:  if (c256++ == 0) ga[0] = p; else be[0] = p; break;
            case 512:  if (c512++ == 0) ga[1] = p; else be[1] = p; break;
            case 1024: if (c1024++ == 0) ga[2] = p; else be[2] = p; break;
            case 255:  if (c255 < 3) b1[c255++] = p; break;
        }
    }
    float* out = (float*)d_out;

    zero_misc<<<128, 256>>>();

    conv3x3<128, 256, 76><<<dim3(722, 4), 256>>>(f0, w3[0], ga[0], be[0]);
    pred_decode<256, 76><<<5776, 256>>>(w1[0], b1[0], 0, 8.0f, 0);

    conv3x3<256, 512, 38><<<dim3(181, 8), 256>>>(f1, w3[1], ga[1], be[1]);
    pred_decode<512, 38><<<1444, 256>>>(w1[1], b1[1], 17328, 16.0f, 1);

    conv3x3<512, 1024, 19><<<dim3(46, 16), 256>>>(f2, w3[2], ga[2], be[2]);
    pred_decode<1024, 19><<<361, 256>>>(w1[2], b1[2], 21660, 32.0f, 2);

    hist1_kernel<<<dim3(445, 8), 256>>>();
    scan1_kernel<<<8, 1024>>>();
    hist2_kernel<<<dim3(445, 8), 256>>>();
    scan2_kernel<<<8, 1024>>>();
    compact_kernel<<<dim3(445, 8), 256>>>();
    nms_kernel<<<8, 512>>>(out);
}

// round 4
// speedup vs baseline: 1.0584x; 1.0584x over previous
#include <cuda_runtime.h>
#include <cstddef>

// ---------------- problem constants ----------------
#define BATCH 8
#define NCLS 80
#define ATOT 22743            // 76*76*3 + 38*38*3 + 19*19*3
#define NFLAT (ATOT * NCLS)   // 1,819,440 per batch
#define PRE_NMS 400
#define MAX_DET 100

// ---------------- static scratch (no runtime allocs allowed) ----------------
__device__ float g_x[46208 * 256];                         // tower activations (max level 0), 47MB
__device__ float g_boxes[BATCH * ATOT * 4];                // decoded boxes
__device__ float g_scores[(size_t)BATCH * NFLAT];          // decoded scores, 58MB
__device__ unsigned g_hist1[BATCH * 4096];
__device__ unsigned g_hist2[BATCH * 4096];
__device__ unsigned g_b1[BATCH];
__device__ unsigned g_prefix1[BATCH];
__device__ unsigned g_pivot[BATCH];
__device__ unsigned g_cnt[BATCH];
__device__ unsigned long long g_cand[BATCH * 8192];

__constant__ float c_anchors[3][3][2] = {
    {{12.f, 16.f}, {19.f, 36.f}, {40.f, 28.f}},
    {{36.f, 75.f}, {76.f, 55.f}, {72.f, 146.f}},
    {{142.f, 110.f}, {192.f, 243.f}, {459.f, 401.f}}};

__device__ __forceinline__ float sigmoidf_(float x) { return 1.0f / (1.0f + expf(-x)); }

// ---------------- init ----------------
__global__ void zero_misc() {
    int i = blockIdx.x * blockDim.x + threadIdx.x;
    if (i < BATCH * 4096) { g_hist1[i] = 0u; g_hist2[i] = 0u; }
    if (i < BATCH) {
        g_cnt[i] = 0u;
        g_b1[i] = 0u;
        g_prefix1[i] = 0u;
        g_pivot[i] = 0u;
    }
}

// ---------------- fused conv3x3 + scale/bias + leaky-relu ----------------
// Implicit-GEMM: M = BATCH*H*H pixels, N = COUT, K = 9*CIN.
// BM=128, BN=128, BK=16, 256 threads, 8x8 microtile, double-buffered smem.
// LDS traffic: 64B per 64 FMA per thread-k -> 1 B/FMA (crossbar budget).
template <int CIN, int COUT, int HH>
__global__ __launch_bounds__(256, 2) void conv3x3(const float* __restrict__ in,
                                                  const float* __restrict__ w,
                                                  const float* __restrict__ gamma,
                                                  const float* __restrict__ beta) {
    constexpr int M = BATCH * HH * HH;
    constexpr int KTOT = 9 * CIN;
    constexpr int NT = KTOT / 16;
    __shared__ float As[2][16][132];  // [buf][k][m]
    __shared__ float Bs[2][16][132];  // [buf][k][n]

    const int tid = threadIdx.x;
    const int bm0 = blockIdx.x * 128;
    const int bn0 = blockIdx.y * 128;

    // A-load per-thread coords: 2 float4 loads, row m = l*64 + tid/4, kq = (tid&3)*4
    const int kq = (tid & 3) * 4;
    int aB[2], aOy[2], aOx[2];
    bool aValid[2];
#pragma unroll
    for (int l = 0; l < 2; l++) {
        int m = l * 64 + (tid >> 2);
        int gm = bm0 + m;
        aValid[l] = (gm < M);
        int gmc = aValid[l] ? gm : 0;
        aB[l] = gmc / (HH * HH);
        int rr = gmc % (HH * HH);
        aOy[l] = rr / HH;
        aOx[l] = rr % HH;
    }
    // B-load: k = l*8 + tid/32, n = (tid&31)*4
    const int bK = tid >> 5;
    const int bN = (tid & 31) * 4;

    const int ty = tid >> 4;  // 0..15
    const int tx = tid & 15;  // 0..15

    float acc[8][8] = {};
    float4 aReg[2], bReg[2];

    auto loadTile = [&](int kt) {
        const int kk = kt * 16;
        const int tap = kk / CIN;  // 16 | CIN so one 3x3 tap per tile
        const int ky = tap / 3, kx = tap % 3;
        const int ciB = kk % CIN;
#pragma unroll
        for (int l = 0; l < 2; l++) {
            int iy = aOy[l] + ky - 1;
            int ix = aOx[l] + kx - 1;
            float4 v = make_float4(0.f, 0.f, 0.f, 0.f);
            if (aValid[l] && iy >= 0 && iy < HH && ix >= 0 && ix < HH)
                v = *(const float4*)&in[(((size_t)aB[l] * HH + iy) * HH + ix) * CIN + ciB + kq];
            aReg[l] = v;
            bReg[l] = *(const float4*)&w[(size_t)(kk + l * 8 + bK) * COUT + bn0 + bN];
        }
    };
    auto storeTile = [&](int buf) {
#pragma unroll
        for (int l = 0; l < 2; l++) {
            int m = l * 64 + (tid >> 2);
            As[buf][kq + 0][m] = aReg[l].x;
            As[buf][kq + 1][m] = aReg[l].y;
            As[buf][kq + 2][m] = aReg[l].z;
            As[buf][kq + 3][m] = aReg[l].w;
            *(float4*)&Bs[buf][l * 8 + bK][bN] = bReg[l];
        }
    };

    loadTile(0);
    storeTile(0);
    __syncthreads();

    for (int kt = 0; kt < NT; kt++) {
        const int buf = kt & 1;
        if (kt + 1 < NT) loadTile(kt + 1);
#pragma unroll
        for (int k = 0; k < 16; k++) {
            float4 a0 = *(float4*)&As[buf][k][ty * 4];
            float4 a1 = *(float4*)&As[buf][k][ty * 4 + 64];
            float4 b0 = *(float4*)&Bs[buf][k][tx * 4];
            float4 b1 = *(float4*)&Bs[buf][k][tx * 4 + 64];
            float av[8] = {a0.x, a0.y, a0.z, a0.w, a1.x, a1.y, a1.z, a1.w};
            float bv[8] = {b0.x, b0.y, b0.z, b0.w, b1.x, b1.y, b1.z, b1.w};
#pragma unroll
            for (int i = 0; i < 8; i++)
#pragma unroll
                for (int j = 0; j < 8; j++) acc[i][j] += av[i] * bv[j];
        }
        if (kt + 1 < NT) {
            storeTile(buf ^ 1);
            __syncthreads();
        }
    }

    // epilogue: scale/bias + leaky relu
    float4 g0 = *(const float4*)&gamma[bn0 + tx * 4];
    float4 g1 = *(const float4*)&gamma[bn0 + tx * 4 + 64];
    float4 e0 = *(const float4*)&beta[bn0 + tx * 4];
    float4 e1 = *(const float4*)&beta[bn0 + tx * 4 + 64];
    float gv[8] = {g0.x, g0.y, g0.z, g0.w, g1.x, g1.y, g1.z, g1.w};
    float ev[8] = {e0.x, e0.y, e0.z, e0.w, e1.x, e1.y, e1.z, e1.w};
#pragma unroll
    for (int i = 0; i < 8; i++) {
        int gm = bm0 + ty * 4 + (i & 3) + (i >> 2) * 64;
        if (gm < M) {
            float t[8];
#pragma unroll
            for (int j = 0; j < 8; j++) {
                float v = acc[i][j] * gv[j] + ev[j];
                t[j] = v > 0.f ? v : 0.1f * v;
            }
            *(float4*)&g_x[(size_t)gm * COUT + bn0 + tx * 4] =
                make_float4(t[0], t[1], t[2], t[3]);
            *(float4*)&g_x[(size_t)gm * COUT + bn0 + tx * 4 + 64] =
                make_float4(t[4], t[5], t[6], t[7]);
        }
    }
}

// ---------------- 1x1 conv (255 ch) + bias + decode ----------------
// Each block handles 8 pixels; thread t<255 computes pred channel t for all 8.
template <int HD, int HH>
__global__ __launch_bounds__(256) void pred_decode(const float* __restrict__ w1,
                                                   const float* __restrict__ bias,
                                                   int levelOff, float stride, int alevel) {
    constexpr int P = 8;
    __shared__ float xsh[P][HD];
    __shared__ float psh[P][256];
    const int tid = threadIdx.x;
    const int pix0 = blockIdx.x * P;

    for (int id = tid; id < P * (HD / 4); id += 256) {
        int p = id / (HD / 4);
        int r = id % (HD / 4);
        *(float4*)&xsh[p][r * 4] = *(const float4*)&g_x[(size_t)(pix0 + p) * HD + r * 4];
    }
    __syncthreads();

    if (tid < 255) {
        float acc[P];
        float bb = bias[tid];
#pragma unroll
        for (int p = 0; p < P; p++) acc[p] = bb;
#pragma unroll 4
        for (int k = 0; k < HD; k++) {
            float wv = w1[(size_t)k * 255 + tid];
#pragma unroll
            for (int p = 0; p < P; p++) acc[p] += xsh[p][k] * wv;
        }
#pragma unroll
        for (int p = 0; p < P; p++) psh[p][tid] = acc[p];
    }
    __syncthreads();

    // scores: 8 pixels * 3 anchors * 80 classes
    for (int wi = tid; wi < P * 240; wi += 256) {
        int p = wi / 240, r = wi % 240;
        int a = r / 80, c = r % 80;
        float so = sigmoidf_(psh[p][a * 85 + 4]);
        float sc = sigmoidf_(psh[p][a * 85 + 5 + c]);
        int pix = pix0 + p;
        int b = pix / (HH * HH);
        int rr = pix % (HH * HH);
        size_t aidx = (size_t)b * ATOT + levelOff + rr * 3 + a;
        g_scores[aidx * NCLS + c] = so * sc;
    }
    // boxes: 8 pixels * 3 anchors
    for (int wi = tid; wi < P * 3; wi += 256) {
        int p = wi / 3, a = wi % 3;
        int pix = pix0 + p;
        int b = pix / (HH * HH);
        int rr = pix % (HH * HH);
        int oy = rr / HH, ox = rr % HH;
        float tx = psh[p][a * 85 + 0];
        float ty = psh[p][a * 85 + 1];
        float tw = psh[p][a * 85 + 2];
        float th = psh[p][a * 85 + 3];
        float cx = ((sigmoidf_(tx) * 1.05f - 0.025f) + (float)ox) * stride;
        float cy = ((sigmoidf_(ty) * 1.05f - 0.025f) + (float)oy) * stride;
        float bw = expf(tw) * c_anchors[alevel][a][0];
        float bh = expf(th) * c_anchors[alevel][a][1];
        size_t aidx = (size_t)b * ATOT + levelOff + rr * 3 + a;
        float* bp = &g_boxes[aidx * 4];
        bp[0] = cx - 0.5f * bw;
        bp[1] = cy - 0.5f * bh;
        bp[2] = cx + 0.5f * bw;
        bp[3] = cy + 0.5f * bh;
    }
}

// ---------------- top-400 selection: 2-level radix histogram on float bits ----------------
__global__ void hist1_kernel() {
    __shared__ unsigned h[4096];
    for (int i = threadIdx.x; i < 4096; i += blockDim.x) h[i] = 0u;
    __syncthreads();
    int b = blockIdx.y;
    const float* sc = &g_scores[(size_t)b * NFLAT];
    int start = blockIdx.x * 4096;
    int end = min(start + 4096, NFLAT);
    for (int i = start + (int)threadIdx.x; i < end; i += blockDim.x) {
        float s = sc[i];
        unsigned bits = (s >= 0.05f) ? __float_as_uint(s) : 0u;
        atomicAdd(&h[bits >> 20], 1u);
    }
    __syncthreads();
    for (int i = threadIdx.x; i < 4096; i += blockDim.x)
        if (h[i]) atomicAdd(&g_hist1[b * 4096 + i], h[i]);
}

__global__ void scan1_kernel() {
    __shared__ unsigned s[1024];
    int b = blockIdx.x, tid = threadIdx.x;
    unsigned v[4], sum = 0;
#pragma unroll
    for (int j = 0; j < 4; j++) {
        v[j] = g_hist1[b * 4096 + 4095 - (tid * 4 + j)];
        sum += v[j];
    }
    s[tid] = sum;
    __syncthreads();
    for (int off = 1; off < 1024; off <<= 1) {
        unsigned t = (tid >= off) ? s[tid - off] : 0u;
        __syncthreads();
        s[tid] += t;
        __syncthreads();
    }
    unsigned excl = s[tid] - sum;
    unsigned cum = excl;
#pragma unroll
    for (int j = 0; j < 4; j++) {
        if (cum < PRE_NMS && cum + v[j] >= PRE_NMS) {
            g_b1[b] = 4095 - (tid * 4 + j);
            g_prefix1[b] = cum;
        }
        cum += v[j];
    }
}

__global__ void hist2_kernel() {
    __shared__ unsigned h[4096];
    for (int i = threadIdx.x; i < 4096; i += blockDim.x) h[i] = 0u;
    __syncthreads();
    int b = blockIdx.y;
    unsigned b1 = g_b1[b];
    const float* sc = &g_scores[(size_t)b * NFLAT];
    int start = blockIdx.x * 4096;
    int end = min(start + 4096, NFLAT);
    for (int i = start + (int)threadIdx.x; i < end; i += blockDim.x) {
        float s = sc[i];
        unsigned bits = (s >= 0.05f) ? __float_as_uint(s) : 0u;
        if ((bits >> 20) == b1) atomicAdd(&h[(bits >> 8) & 0xFFFu], 1u);
    }
    __syncthreads();
    for (int i = threadIdx.x; i < 4096; i += blockDim.x)
        if (h[i]) atomicAdd(&g_hist2[b * 4096 + i], h[i]);
}

__global__ void scan2_kernel() {
    __shared__ unsigned s[1024];
    int b = blockIdx.x, tid = threadIdx.x;
    unsigned target = PRE_NMS - g_prefix1[b];  // >= 1 by construction
    unsigned v[4], sum = 0;
#pragma unroll
    for (int j = 0; j < 4; j++) {
        v[j] = g_hist2[b * 4096 + 4095 - (tid * 4 + j)];
        sum += v[j];
    }
    s[tid] = sum;
    __syncthreads();
    for (int off = 1; off < 1024; off <<= 1) {
        unsigned t = (tid >= off) ? s[tid - off] : 0u;
        __syncthreads();
        s[tid] += t;
        __syncthreads();
    }
    unsigned excl = s[tid] - sum;
    unsigned cum = excl;
#pragma unroll
    for (int j = 0; j < 4; j++) {
        if (cum < target && cum + v[j] >= target) {
            g_pivot[b] = (g_b1[b] << 12) | (unsigned)(4095 - (tid * 4 + j));
        }
        cum += v[j];
    }
}

__global__ void compact_kernel() {
    int b = blockIdx.y;
    unsigned pivot = g_pivot[b];
    const float* sc = &g_scores[(size_t)b * NFLAT];
    int start = blockIdx.x * 4096;
    int end = min(start + 4096, NFLAT);
    for (int i = start + (int)threadIdx.x; i < end; i += blockDim.x) {
        float s = sc[i];
        unsigned bits = (s >= 0.05f) ? __float_as_uint(s) : 0u;
        if ((bits >> 8) >= pivot) {
            unsigned pos = atomicAdd(&g_cnt[b], 1u);
            if (pos < 8192)
                g_cand[b * 8192 + pos] =
                    ((unsigned long long)bits << 32) |
                    (unsigned long long)(0xFFFFFFFFu - (unsigned)i);
        }
    }
}

// ---------------- exact top-k sort + greedy NMS + final top-100 ----------------
__global__ __launch_bounds__(512) void nms_kernel(float* __restrict__ out) {
    constexpr int NC = 2048;
    __shared__ unsigned long long keys[NC];
    __shared__ float boSh[PRE_NMS][4];
    __shared__ float areaSh[PRE_NMS];
    __shared__ float scSh[PRE_NMS];
    __shared__ int keepSh[PRE_NMS];
    __shared__ int aiSh[PRE_NMS];
    __shared__ int ciSh[PRE_NMS];
    __shared__ unsigned long long key2[512];

    int b = blockIdx.x;
    int tid = threadIdx.x;
    int cnt = min((int)g_cnt[b], NC);
    for (int i = tid; i < NC; i += 512)
        keys[i] = (i < cnt) ? g_cand[b * 8192 + i] : 0ull;
    __syncthreads();

    // bitonic ascending sort over NC composite keys (score_bits, ~flat_idx)
    for (int k = 2; k <= NC; k <<= 1) {
        for (int j = k >> 1; j > 0; j >>= 1) {
            for (int i = tid; i < NC; i += 512) {
                int ixj = i ^ j;
                if (ixj > i) {
                    bool up = ((i & k) == 0);
                    unsigned long long a = keys[i], c = keys[ixj];
                    if (up ? (a > c) : (a < c)) { keys[i] = c; keys[ixj] = a; }
                }
            }
            __syncthreads();
        }
    }

    // extract top-400 (descending), build offset boxes exactly like reference
    if (tid < PRE_NMS) {
        unsigned long long key = keys[NC - 1 - tid];
        unsigned bits = (unsigned)(key >> 32);
        unsigned flat = 0xFFFFFFFFu - (unsigned)(key & 0xFFFFFFFFull);
        if (key == 0ull) { bits = 0u; flat = 0u; }
        float s = __uint_as_float(bits);
        int a = (int)(flat / NCLS);
        int c = (int)(flat % NCLS);
        const float* bp = &g_boxes[((size_t)b * ATOT + a) * 4];
        float off = (float)c * 1216.0f;  // c * 2*IMG_SIZE
        float x0 = bp[0] + off, y0 = bp[1] + off;
        float x1 = bp[2] + off, y1 = bp[3] + off;
        boSh[tid][0] = x0; boSh[tid][1] = y0; boSh[tid][2] = x1; boSh[tid][3] = y1;
        areaSh[tid] = (x1 - x0) * (y1 - y0);
        scSh[tid] = s;
        keepSh[tid] = 1;
        aiSh[tid] = a;
        ciSh[tid] = c;
    }
    __syncthreads();

    // greedy suppression, iteration order = score rank (matches fori_loop)
    for (int i = 0; i < PRE_NMS; i++) {
        bool act = (keepSh[i] != 0) && (scSh[i] > 0.f);
        if (act && tid > i && tid < PRE_NMS) {
            float lx = fmaxf(boSh[i][0], boSh[tid][0]);
            float ly = fmaxf(boSh[i][1], boSh[tid][1]);
            float rx = fminf(boSh[i][2], boSh[tid][2]);
            float ry = fminf(boSh[i][3], boSh[tid][3]);
            float w = fmaxf(rx - lx, 0.f), h = fmaxf(ry - ly, 0.f);
            float inter = w * h;
            float iou = inter / (areaSh[i] + areaSh[tid] - inter + 1e-7f);
            if (iou > 0.5f) keepSh[tid] = 0;
        }
        __syncthreads();
    }

    // final scores + stable top-100
    {
        unsigned long long key = 0ull;
        if (tid < PRE_NMS) {
            float fin = (keepSh[tid] && scSh[tid] > 0.f) ? scSh[tid] : 0.f;
            key = ((unsigned long long)__float_as_uint(fin) << 32) |
                  (unsigned long long)(0xFFFFFFFFu - (unsigned)tid);
        }
        key2[tid] = key;
    }
    __syncthreads();
    for (int k = 2; k <= 512; k <<= 1) {
        for (int j = k >> 1; j > 0; j >>= 1) {
            int i = tid;
            int ixj = i ^ j;
            if (ixj > i) {
                bool up = ((i & k) == 0);
                unsigned long long a = key2[i], c = key2[ixj];
                if (up ? (a > c) : (a < c)) { key2[i] = c; key2[ixj] = a; }
            }
            __syncthreads();
        }
    }

    if (tid < MAX_DET) {
        unsigned long long key = key2[511 - tid];
        unsigned sb = (unsigned)(key >> 32);
        int pos = (int)(0xFFFFFFFFu - (unsigned)(key & 0xFFFFFFFFull));
        int a = aiSh[pos], c = ciSh[pos];
        const float* bp = &g_boxes[((size_t)b * ATOT + a) * 4];
        int d = b * MAX_DET + tid;
        out[d * 4 + 0] = bp[0];
        out[d * 4 + 1] = bp[1];
        out[d * 4 + 2] = bp[2];
        out[d * 4 + 3] = bp[3];
        out[BATCH * MAX_DET * 4 + d] = __uint_as_float(sb);
        out[BATCH * MAX_DET * 4 + BATCH * MAX_DET + d] = (float)c;
    }
}

// ---------------- launcher ----------------
extern "C" void kernel_launch(void* const* d_in, const int* in_sizes, int n_in,
                              void* d_out, int out_size) {
    (void)out_size;
    const float *f0 = nullptr, *f1 = nullptr, *f2 = nullptr;
    const float *w3[3] = {}, *ga[3] = {}, *be[3] = {}, *w1[3] = {}, *b1[3] = {};
    int c256 = 0, c512 = 0, c1024 = 0, c255 = 0;
    for (int i = 0; i < n_in; i++) {
        const float* p = (const float*)d_in[i];
        switch (in_sizes[i]) {
            case 5914624: f0 = p; break;                 // 8*76*76*128
            case 2957312: f1 = p; break;                 // 8*38*38*256
            case 1478656: f2 = p; break;                 // 8*19*19*512
            case 294912:  w3[0] = p; break;              // 3*3*128*256
            case 1179648: w3[1] = p; break;              // 3*3*256*512
            case 4718592: w3[2] = p; break;              // 3*3*512*1024
            case 65280:   w1[0] = p; break;              // 256*255
            case 130560:  w1[1] = p; break;              // 512*255
            case 261120:  w1[2] = p; break;              // 1024*255
            case 256:  if (c256++ == 0) ga[0] = p; else be[0] = p; break;
            case 512:  if (c512++ == 0) ga[1] = p; else be[1] = p; break;
            case 1024: if (c1024++ == 0) ga[2] = p; else be[2] = p; break;
            case 255:  if (c255 < 3) b1[c255++] = p; break;
        }
    }
    float* out = (float*)d_out;

    zero_misc<<<128, 256>>>();

    conv3x3<128, 256, 76><<<dim3(361, 2), 256>>>(f0, w3[0], ga[0], be[0]);
    pred_decode<256, 76><<<5776, 256>>>(w1[0], b1[0], 0, 8.0f, 0);

    conv3x3<256, 512, 38><<<dim3(91, 4), 256>>>(f1, w3[1], ga[1], be[1]);
    pred_decode<512, 38><<<1444, 256>>>(w1[1], b1[1], 17328, 16.0f, 1);

    conv3x3<512, 1024, 19><<<dim3(23, 8), 256>>>(f2, w3[2], ga[2], be[2]);
    pred_decode<1024, 19><<<361, 256>>>(w1[2], b1[2], 21660, 32.0f, 2);

    hist1_kernel<<<dim3(445, 8), 256>>>();
    scan1_kernel<<<8, 1024>>>();
    hist2_kernel<<<dim3(445, 8), 256>>>();
    scan2_kernel<<<8, 1024>>>();
    compact_kernel<<<dim3(445, 8), 256>>>();
    nms_kernel<<<8, 512>>>(out);
}